// round 1
// baseline (speedup 1.0000x reference)
#include <cuda_runtime.h>

#define Bb 8
#define Nn 4096
#define Cc 8
#define Tt 256
#define NPB 64      // n-values per block in the reduction kernel
#define TI 16       // output rows per block in the epilogue kernel

// Tiny cross-block accumulators (allocation-free scratch).
__device__ float g_xu1[Bb * Cc * Tt];  // x_u1 stored as [b][c][t]  (logical x_u1[b,t,c])
__device__ float g_M  [Bb * Cc * Tt];  // M[b,c,s]

// ---------------------------------------------------------------------------
// Kernel 0: zero the accumulators (graph replays need fresh zeros each launch)
// ---------------------------------------------------------------------------
__global__ void k_zero() {
    int i = blockIdx.x * blockDim.x + threadIdx.x;
    if (i < Bb * Cc * Tt) { g_xu1[i] = 0.f; g_M[i] = 0.f; }
}

// ---------------------------------------------------------------------------
// Kernel 1: single streaming pass over x (256 MB).
//   rhs_n[t]   = sum_c x[b,n,c,t] * u3[c]
//   x_u1[b,c,t] += x[b,n,c,t] * u1[n]
//   M[b,c,t]    += u2[c,n] * rhs_n[t]
// Each thread owns one t; all accumulators live in registers; one atomicAdd
// per (c,t) pair per block at the end.
// ---------------------------------------------------------------------------
__global__ __launch_bounds__(256) void k_reduce(
    const float* __restrict__ x,  const float* __restrict__ u1,
    const float* __restrict__ u2, const float* __restrict__ u3)
{
    __shared__ float s_u1[NPB];
    __shared__ float s_u2[Cc * NPB];

    const int t  = threadIdx.x;          // 0..255
    const int b  = blockIdx.y;
    const int n0 = blockIdx.x * NPB;

    if (t < NPB) s_u1[t] = u1[n0 + t];
    for (int i = t; i < Cc * NPB; i += 256) {
        int c = i / NPB, nn = i % NPB;
        s_u2[i] = u2[c * Nn + n0 + nn];
    }
    float ru3[Cc];
#pragma unroll
    for (int c = 0; c < Cc; c++) ru3[c] = u3[c];
    __syncthreads();

    const float* xb = x + (((size_t)b * Nn + n0) * Cc) * Tt;

    float ax[Cc], am[Cc];
#pragma unroll
    for (int c = 0; c < Cc; c++) { ax[c] = 0.f; am[c] = 0.f; }

#pragma unroll 2
    for (int n = 0; n < NPB; n++) {
        const float* xn = xb + (size_t)n * (Cc * Tt);
        float vals[Cc];
#pragma unroll
        for (int c = 0; c < Cc; c++) vals[c] = xn[c * Tt + t];   // coalesced

        float r = 0.f;
#pragma unroll
        for (int c = 0; c < Cc; c++) r += vals[c] * ru3[c];

        const float un = s_u1[n];
#pragma unroll
        for (int c = 0; c < Cc; c++) {
            ax[c] += vals[c] * un;
            am[c] += s_u2[c * NPB + n] * r;
        }
    }

    float* gx = g_xu1 + b * Cc * Tt;
    float* gm = g_M   + b * Cc * Tt;
#pragma unroll
    for (int c = 0; c < Cc; c++) {
        atomicAdd(&gx[c * Tt + t], ax[c]);
        atomicAdd(&gm[c * Tt + t], am[c]);
    }
}

// ---------------------------------------------------------------------------
// Kernel 2: fused epilogue.
//   product[b,k,j] = sum_c x_u1[b,c,k] * M[b,c,j] + bias[k,j]
//   S = sigmoid(product)
//   E[b,i,j] = sum_k v[i,k] * S[b,k,j]
//   out = softmax_j(E)
// One block per (b, 16-row i-tile). Thread j owns column j; E accumulates in
// registers; softmax via warp-per-row reduction.
// ---------------------------------------------------------------------------
__global__ __launch_bounds__(256) void k_attn(
    const float* __restrict__ bias, const float* __restrict__ v,
    float* __restrict__ out)
{
    __shared__ float s_X[Cc * Tt];    // x_u1 transposed: s_X[k*Cc + c]
    __shared__ float s_M[Cc * Tt];    // M[b][c][j]
    __shared__ float s_buf[TI * Tt];  // first: v transposed [k][il]; then E [il][j]

    const int j  = threadIdx.x;       // 0..255 (column)
    const int b  = blockIdx.y;
    const int i0 = blockIdx.x * TI;

    for (int idx = j; idx < Cc * Tt; idx += 256) {
        int c = idx / Tt, k = idx % Tt;
        s_X[k * Cc + c] = g_xu1[b * Cc * Tt + idx];
        s_M[idx]        = g_M  [b * Cc * Tt + idx];
    }
    for (int idx = j; idx < TI * Tt; idx += 256) {
        int il = idx / Tt, k = idx % Tt;
        s_buf[k * TI + il] = v[(i0 + il) * Tt + k];
    }
    __syncthreads();

    float rm[Cc];
#pragma unroll
    for (int c = 0; c < Cc; c++) rm[c] = s_M[c * Tt + j];

    float acc[TI];
#pragma unroll
    for (int il = 0; il < TI; il++) acc[il] = 0.f;

    for (int k = 0; k < Tt; k++) {
        float4 x0 = *(const float4*)&s_X[k * Cc + 0];   // broadcast LDS
        float4 x1 = *(const float4*)&s_X[k * Cc + 4];
        float p = x0.x * rm[0] + x0.y * rm[1] + x0.z * rm[2] + x0.w * rm[3]
                + x1.x * rm[4] + x1.y * rm[5] + x1.z * rm[6] + x1.w * rm[7];
        p += bias[k * Tt + j];
        float s = 1.f / (1.f + __expf(-p));

        const float4* vk = (const float4*)&s_buf[k * TI];
#pragma unroll
        for (int q = 0; q < TI / 4; q++) {
            float4 vv = vk[q];
            acc[q * 4 + 0] += vv.x * s;
            acc[q * 4 + 1] += vv.y * s;
            acc[q * 4 + 2] += vv.z * s;
            acc[q * 4 + 3] += vv.w * s;
        }
    }

    __syncthreads();  // done reading s_buf as v
#pragma unroll
    for (int il = 0; il < TI; il++) s_buf[il * Tt + j] = acc[il];
    __syncthreads();

    const int w = j >> 5, lane = j & 31;
    for (int row = w; row < TI; row += 8) {
        float m = -1e30f;
        for (int q = lane; q < Tt; q += 32) m = fmaxf(m, s_buf[row * Tt + q]);
#pragma unroll
        for (int off = 16; off > 0; off >>= 1)
            m = fmaxf(m, __shfl_xor_sync(0xffffffffu, m, off));

        float e[Tt / 32];
        float sum = 0.f;
#pragma unroll
        for (int qi = 0; qi < Tt / 32; qi++) {
            e[qi] = __expf(s_buf[row * Tt + qi * 32 + lane] - m);
            sum += e[qi];
        }
#pragma unroll
        for (int off = 16; off > 0; off >>= 1)
            sum += __shfl_xor_sync(0xffffffffu, sum, off);

        float inv = __frcp_rn(sum);
        size_t o = ((size_t)b * Tt + (i0 + row)) * Tt;
#pragma unroll
        for (int qi = 0; qi < Tt / 32; qi++)
            out[o + qi * 32 + lane] = e[qi] * inv;
    }
}

// ---------------------------------------------------------------------------
extern "C" void kernel_launch(void* const* d_in, const int* in_sizes, int n_in,
                              void* d_out, int out_size)
{
    const float* x  = (const float*)d_in[0];
    const float* u1 = (const float*)d_in[1];
    const float* u2 = (const float*)d_in[2];
    const float* u3 = (const float*)d_in[3];
    const float* bb = (const float*)d_in[4];
    const float* v  = (const float*)d_in[5];
    float* out = (float*)d_out;

    k_zero<<<(Bb * Cc * Tt + 255) / 256, 256>>>();

    dim3 g1(Nn / NPB, Bb);          // 64 x 8 = 512 blocks
    k_reduce<<<g1, 256>>>(x, u1, u2, u3);

    dim3 g2(Tt / TI, Bb);           // 16 x 8 = 128 blocks
    k_attn<<<g2, 256>>>(bb, v, out);
}

// round 2
// speedup vs baseline: 1.0864x; 1.0864x over previous
#include <cuda_runtime.h>

#define Bb 8
#define Nn 4096
#define Cc 8
#define Tt 256
#define NPB 32                 // n-values per block in k_reduce
#define NBLK (Nn / NPB)        // 128 n-blocks per batch
#define TI 8                   // output rows per block in k_attn
#define TQ (Tt / 4)            // 64 float4 quads over t

// Per-block partial sums: [Bb*NBLK blocks][2 arrays][Cc][TQ] float4 = 16 MB (L2-resident)
__device__ float4 g_part[Bb * NBLK * 2 * Cc * TQ];
__device__ float  g_xu1[Bb * Cc * Tt];   // x_u1 as [b][c][t]
__device__ float  g_M  [Bb * Cc * Tt];   // M[b][c][s]

// ---------------------------------------------------------------------------
// Kernel 1: single streaming pass over x (256 MB), vectorized float4.
// Warp layout: lane = sub*8 + r ; sub = n-sublane (0..3), quad q = warp*8 + r.
// Each LDG.128 covers 4 n-values x 128B. Cross-sub reduction via shfl.
// ---------------------------------------------------------------------------
__global__ __launch_bounds__(256, 2) void k_reduce(
    const float* __restrict__ x,  const float* __restrict__ u1,
    const float* __restrict__ u2, const float* __restrict__ u3)
{
    __shared__ float s_u1[NPB];
    __shared__ float s_u2[Cc * NPB];

    const int tid  = threadIdx.x;
    const int lane = tid & 31;
    const int warp = tid >> 5;
    const int sub  = lane >> 3;               // 0..3
    const int q    = warp * 8 + (lane & 7);   // 0..63

    const int b  = blockIdx.y;
    const int n0 = blockIdx.x * NPB;

    if (tid < NPB) s_u1[tid] = u1[n0 + tid];
    {   // Cc*NPB == 256 == blockDim
        int c  = tid >> 5;
        int nn = tid & 31;
        s_u2[tid] = u2[c * Nn + n0 + nn];
    }
    float c3[Cc];
#pragma unroll
    for (int c = 0; c < Cc; c++) c3[c] = u3[c];
    __syncthreads();

    const float4* xb = (const float4*)x + ((size_t)b * Nn + n0) * (Cc * TQ);

    float4 ax[Cc], am[Cc];
#pragma unroll
    for (int c = 0; c < Cc; c++) {
        ax[c] = make_float4(0.f, 0.f, 0.f, 0.f);
        am[c] = make_float4(0.f, 0.f, 0.f, 0.f);
    }

#pragma unroll
    for (int ni = 0; ni < NPB / 4; ni++) {
        const int n = ni * 4 + sub;
        const float4* xn = xb + (size_t)n * (Cc * TQ) + q;

        float4 vals[Cc];
#pragma unroll
        for (int c = 0; c < Cc; c++) vals[c] = xn[c * TQ];

        float4 r = make_float4(0.f, 0.f, 0.f, 0.f);
#pragma unroll
        for (int c = 0; c < Cc; c++) {
            r.x += vals[c].x * c3[c];
            r.y += vals[c].y * c3[c];
            r.z += vals[c].z * c3[c];
            r.w += vals[c].w * c3[c];
        }
        const float un = s_u1[n];
#pragma unroll
        for (int c = 0; c < Cc; c++) {
            ax[c].x += vals[c].x * un;
            ax[c].y += vals[c].y * un;
            ax[c].z += vals[c].z * un;
            ax[c].w += vals[c].w * un;
            const float w = s_u2[c * NPB + n];
            am[c].x += r.x * w;
            am[c].y += r.y * w;
            am[c].z += r.z * w;
            am[c].w += r.w * w;
        }
    }

    // Reduce the 4 n-sublanes (lane bits 3,4) via shuffles.
#pragma unroll
    for (int c = 0; c < Cc; c++) {
#pragma unroll
        for (int off = 8; off < 32; off <<= 1) {
            ax[c].x += __shfl_xor_sync(0xffffffffu, ax[c].x, off);
            ax[c].y += __shfl_xor_sync(0xffffffffu, ax[c].y, off);
            ax[c].z += __shfl_xor_sync(0xffffffffu, ax[c].z, off);
            ax[c].w += __shfl_xor_sync(0xffffffffu, ax[c].w, off);
            am[c].x += __shfl_xor_sync(0xffffffffu, am[c].x, off);
            am[c].y += __shfl_xor_sync(0xffffffffu, am[c].y, off);
            am[c].z += __shfl_xor_sync(0xffffffffu, am[c].z, off);
            am[c].w += __shfl_xor_sync(0xffffffffu, am[c].w, off);
        }
    }

    if (lane < 8) {  // sub == 0 holds the totals for quad q = warp*8 + lane
        float4* gp = g_part + (size_t)(b * NBLK + blockIdx.x) * (2 * Cc * TQ);
#pragma unroll
        for (int c = 0; c < Cc; c++) gp[c * TQ + q] = ax[c];
#pragma unroll
        for (int c = 0; c < Cc; c++) gp[Cc * TQ + c * TQ + q] = am[c];
    }
}

// ---------------------------------------------------------------------------
// Kernel 2: reduce 128 per-block partials (16 MB, L2-resident) -> g_xu1, g_M
// ---------------------------------------------------------------------------
__global__ __launch_bounds__(128) void k_reduce2()
{
    const int idx = blockIdx.x * 128 + threadIdx.x;   // 0..8191
    const int b   = idx >> 10;
    const int rem = idx & 1023;

    const float4* gp = g_part + (size_t)b * NBLK * (2 * Cc * TQ) + rem;
    float4 s = make_float4(0.f, 0.f, 0.f, 0.f);
#pragma unroll 8
    for (int k = 0; k < NBLK; k++) {
        float4 v = gp[(size_t)k * (2 * Cc * TQ)];
        s.x += v.x; s.y += v.y; s.z += v.z; s.w += v.w;
    }
    if (rem < Cc * TQ) ((float4*)g_xu1)[b * (Cc * TQ) + rem] = s;
    else               ((float4*)g_M  )[b * (Cc * TQ) + rem - Cc * TQ] = s;
}

// ---------------------------------------------------------------------------
// Kernel 3: fused epilogue.
//   product[b,k,j] = sum_c x_u1[b,c,k] * M[b,c,j] + bias[k,j]
//   E[b,i,j] = sum_k v[i,k] * sigmoid(product)[b,k,j]
//   out = softmax_j(E)
// ---------------------------------------------------------------------------
__global__ __launch_bounds__(256) void k_attn(
    const float* __restrict__ bias, const float* __restrict__ v,
    float* __restrict__ out)
{
    __shared__ __align__(16) float s_X[Tt * Cc];   // [k][c] = x_u1[b,k,c]
    __shared__ __align__(16) float s_V[Tt * TI];   // [k][il] = v[i0+il, k]
    __shared__ __align__(16) float s_E[TI * Tt];

    const int j  = threadIdx.x;       // column 0..255
    const int b  = blockIdx.y;
    const int i0 = blockIdx.x * TI;

    for (int idx = j; idx < Cc * Tt; idx += 256) {
        int c = idx >> 8, k = idx & 255;
        s_X[k * Cc + c] = g_xu1[b * Cc * Tt + idx];
    }
    for (int idx = j; idx < TI * Tt; idx += 256) {
        int il = idx >> 8, k = idx & 255;
        s_V[k * TI + il] = v[(i0 + il) * Tt + k];
    }

    float rm[Cc];
#pragma unroll
    for (int c = 0; c < Cc; c++) rm[c] = g_M[b * Cc * Tt + c * Tt + j];

    __syncthreads();

    float acc[TI];
#pragma unroll
    for (int il = 0; il < TI; il++) acc[il] = 0.f;

#pragma unroll 4
    for (int k = 0; k < Tt; k++) {
        float4 x0 = *(const float4*)&s_X[k * Cc + 0];
        float4 x1 = *(const float4*)&s_X[k * Cc + 4];
        float p = bias[k * Tt + j];
        p += x0.x * rm[0] + x0.y * rm[1] + x0.z * rm[2] + x0.w * rm[3]
           + x1.x * rm[4] + x1.y * rm[5] + x1.z * rm[6] + x1.w * rm[7];
        float s = 1.f / (1.f + __expf(-p));

        float4 v0 = *(const float4*)&s_V[k * TI + 0];
        float4 v1 = *(const float4*)&s_V[k * TI + 4];
        acc[0] += v0.x * s;  acc[1] += v0.y * s;
        acc[2] += v0.z * s;  acc[3] += v0.w * s;
        acc[4] += v1.x * s;  acc[5] += v1.y * s;
        acc[6] += v1.z * s;  acc[7] += v1.w * s;
    }

#pragma unroll
    for (int il = 0; il < TI; il++) s_E[il * Tt + j] = acc[il];
    __syncthreads();

    // Softmax: one warp per row (TI == 8 == warps/block)
    const int w = j >> 5, lane = j & 31;
    float m = -1e30f;
#pragma unroll
    for (int qi = 0; qi < Tt / 32; qi++)
        m = fmaxf(m, s_E[w * Tt + qi * 32 + lane]);
#pragma unroll
    for (int off = 16; off > 0; off >>= 1)
        m = fmaxf(m, __shfl_xor_sync(0xffffffffu, m, off));

    float e[Tt / 32];
    float sum = 0.f;
#pragma unroll
    for (int qi = 0; qi < Tt / 32; qi++) {
        e[qi] = __expf(s_E[w * Tt + qi * 32 + lane] - m);
        sum += e[qi];
    }
#pragma unroll
    for (int off = 16; off > 0; off >>= 1)
        sum += __shfl_xor_sync(0xffffffffu, sum, off);

    const float inv = __frcp_rn(sum);
    const size_t o = ((size_t)b * Tt + (i0 + w)) * Tt;
#pragma unroll
    for (int qi = 0; qi < Tt / 32; qi++)
        out[o + qi * 32 + lane] = e[qi] * inv;
}

// ---------------------------------------------------------------------------
extern "C" void kernel_launch(void* const* d_in, const int* in_sizes, int n_in,
                              void* d_out, int out_size)
{
    const float* x  = (const float*)d_in[0];
    const float* u1 = (const float*)d_in[1];
    const float* u2 = (const float*)d_in[2];
    const float* u3 = (const float*)d_in[3];
    const float* bb = (const float*)d_in[4];
    const float* v  = (const float*)d_in[5];
    float* out = (float*)d_out;

    dim3 g1(NBLK, Bb);              // 128 x 8 = 1024 blocks
    k_reduce<<<g1, 256>>>(x, u1, u2, u3);

    k_reduce2<<<64, 128>>>();       // 8192 threads, one float4 output each

    dim3 g3(Tt / TI, Bb);           // 32 x 8 = 256 blocks
    k_attn<<<g3, 256>>>(bb, v, out);
}

// round 3
// speedup vs baseline: 2.0386x; 1.8765x over previous
#include <cuda_runtime.h>

#define Bb 8
#define Nn 4096
#define Cc 8
#define Tt 256
#define NPB 32                 // n-values per block in k_reduce
#define NBLK (Nn / NPB)        // 128 n-blocks per batch
#define TI 16                  // output rows per block in k_attn
#define TQ (Tt / 4)            // 64 float4 quads over t
#define KG 16                  // k's per block in k_sig

// Per-block partial sums: [Bb*NBLK][2][Cc][TQ] float4 = 16 MB (L2-resident)
__device__ float4 g_part[Bb * NBLK * 2 * Cc * TQ];
__device__ float  g_xu1[Bb * Cc * Tt];    // x_u1 as [b][c][t]
__device__ float  g_M  [Bb * Cc * Tt];    // M[b][c][s]
__device__ float  g_S  [Bb * Tt * Tt];    // sigmoid(product + bias), 2 MB

// ---------------------------------------------------------------------------
// Kernel 1: single streaming pass over x (256 MB), vectorized float4.
// Lane layout: lane = c_half*16 + n_sub*8 + qg.
//   c_half (bit4): which 4 of the 8 c-channels this thread accumulates
//   n_sub  (bit3): n parity           qg (bits0-2): quad within warp
// Each thread: 4 LDG.128 per n-iter; r (u3 dot) completed via shfl_xor(16).
// ---------------------------------------------------------------------------
__global__ __launch_bounds__(256, 3) void k_reduce(
    const float* __restrict__ x,  const float* __restrict__ u1,
    const float* __restrict__ u2, const float* __restrict__ u3)
{
    __shared__ float s_u1[NPB];
    __shared__ float s_u2[Cc * NPB];

    const int tid    = threadIdx.x;
    const int lane   = tid & 31;
    const int warp   = tid >> 5;
    const int qg     = lane & 7;
    const int n_sub  = (lane >> 3) & 1;
    const int c_half = lane >> 4;              // 0 or 1
    const int q      = warp * 8 + qg;          // 0..63

    const int b  = blockIdx.y;
    const int n0 = blockIdx.x * NPB;

    if (tid < NPB) s_u1[tid] = u1[n0 + tid];
    {   // Cc*NPB == 256 == blockDim
        int c = tid >> 5, nn = tid & 31;
        s_u2[tid] = u2[c * Nn + n0 + nn];
    }
    float c3[4];
#pragma unroll
    for (int cc = 0; cc < 4; cc++) c3[cc] = u3[c_half * 4 + cc];
    __syncthreads();

    // base: x[b, n0, c_half*4, q*4]
    const float4* xb = (const float4*)x
                     + ((size_t)b * Nn + n0) * (Cc * TQ)
                     + c_half * 4 * TQ + q;

    float4 ax[4], am[4];
#pragma unroll
    for (int cc = 0; cc < 4; cc++) {
        ax[cc] = make_float4(0.f, 0.f, 0.f, 0.f);
        am[cc] = make_float4(0.f, 0.f, 0.f, 0.f);
    }

#pragma unroll
    for (int i = 0; i < NPB / 2; i++) {
        const int n = i * 2 + n_sub;
        const float4* xn = xb + (size_t)n * (Cc * TQ);

        float4 vals[4];
#pragma unroll
        for (int cc = 0; cc < 4; cc++) vals[cc] = xn[cc * TQ];

        float4 r = make_float4(0.f, 0.f, 0.f, 0.f);
#pragma unroll
        for (int cc = 0; cc < 4; cc++) {
            r.x += vals[cc].x * c3[cc];
            r.y += vals[cc].y * c3[cc];
            r.z += vals[cc].z * c3[cc];
            r.w += vals[cc].w * c3[cc];
        }
        // complete the c-sum across the two c-halves
        r.x += __shfl_xor_sync(0xffffffffu, r.x, 16);
        r.y += __shfl_xor_sync(0xffffffffu, r.y, 16);
        r.z += __shfl_xor_sync(0xffffffffu, r.z, 16);
        r.w += __shfl_xor_sync(0xffffffffu, r.w, 16);

        const float un = s_u1[n];
#pragma unroll
        for (int cc = 0; cc < 4; cc++) {
            ax[cc].x += vals[cc].x * un;
            ax[cc].y += vals[cc].y * un;
            ax[cc].z += vals[cc].z * un;
            ax[cc].w += vals[cc].w * un;
            const float w = s_u2[(c_half * 4 + cc) * NPB + n];
            am[cc].x += r.x * w;
            am[cc].y += r.y * w;
            am[cc].z += r.z * w;
            am[cc].w += r.w * w;
        }
    }

    // reduce over n_sub (lane bit 3)
#pragma unroll
    for (int cc = 0; cc < 4; cc++) {
        ax[cc].x += __shfl_xor_sync(0xffffffffu, ax[cc].x, 8);
        ax[cc].y += __shfl_xor_sync(0xffffffffu, ax[cc].y, 8);
        ax[cc].z += __shfl_xor_sync(0xffffffffu, ax[cc].z, 8);
        ax[cc].w += __shfl_xor_sync(0xffffffffu, ax[cc].w, 8);
        am[cc].x += __shfl_xor_sync(0xffffffffu, am[cc].x, 8);
        am[cc].y += __shfl_xor_sync(0xffffffffu, am[cc].y, 8);
        am[cc].z += __shfl_xor_sync(0xffffffffu, am[cc].z, 8);
        am[cc].w += __shfl_xor_sync(0xffffffffu, am[cc].w, 8);
    }

    if (n_sub == 0) {
        float4* gp = g_part + (size_t)(b * NBLK + blockIdx.x) * (2 * Cc * TQ);
#pragma unroll
        for (int cc = 0; cc < 4; cc++) {
            const int c = c_half * 4 + cc;
            gp[c * TQ + q]           = ax[cc];
            gp[Cc * TQ + c * TQ + q] = am[cc];
        }
    }
}

// ---------------------------------------------------------------------------
// Kernel 2: reduce 128 per-block partials (16 MB, L2-resident) -> g_xu1, g_M
// ---------------------------------------------------------------------------
__global__ __launch_bounds__(128) void k_reduce2()
{
    const int idx = blockIdx.x * 128 + threadIdx.x;   // 0..8191
    const int b   = idx >> 10;
    const int rem = idx & 1023;

    const float4* gp = g_part + (size_t)b * NBLK * (2 * Cc * TQ) + rem;
    float4 s = make_float4(0.f, 0.f, 0.f, 0.f);
#pragma unroll 8
    for (int k = 0; k < NBLK; k++) {
        float4 v = gp[(size_t)k * (2 * Cc * TQ)];
        s.x += v.x; s.y += v.y; s.z += v.z; s.w += v.w;
    }
    if (rem < Cc * TQ) ((float4*)g_xu1)[b * (Cc * TQ) + rem] = s;
    else               ((float4*)g_M  )[b * (Cc * TQ) + rem - Cc * TQ] = s;
}

// ---------------------------------------------------------------------------
// Kernel 3: S[b,k,j] = sigmoid( sum_c x_u1[b,c,k]*M[b,c,j] + bias[k,j] )
// Computed ONCE per (b,k,j) — no redundancy. Grid: (Tt/KG, Bb).
// ---------------------------------------------------------------------------
__global__ __launch_bounds__(256) void k_sig(const float* __restrict__ bias)
{
    __shared__ __align__(16) float s_M[Cc * Tt];   // M[b][c][j]
    __shared__ __align__(16) float s_X[KG * Cc];   // x_u1[b][c][k0+kl] as [kl][c]

    const int j  = threadIdx.x;
    const int b  = blockIdx.y;
    const int k0 = blockIdx.x * KG;

    for (int idx = j; idx < Cc * Tt; idx += 256)
        s_M[idx] = g_M[b * Cc * Tt + idx];
    if (j < KG * Cc) {
        int kl = j >> 3, c = j & 7;
        s_X[kl * Cc + c] = g_xu1[b * Cc * Tt + c * Tt + (k0 + kl)];
    }
    __syncthreads();

    float rm[Cc];
#pragma unroll
    for (int c = 0; c < Cc; c++) rm[c] = s_M[c * Tt + j];

#pragma unroll
    for (int kl = 0; kl < KG; kl++) {
        float4 x0 = *(const float4*)&s_X[kl * Cc + 0];
        float4 x1 = *(const float4*)&s_X[kl * Cc + 4];
        float p = bias[(k0 + kl) * Tt + j];
        p += x0.x * rm[0] + x0.y * rm[1] + x0.z * rm[2] + x0.w * rm[3]
           + x1.x * rm[4] + x1.y * rm[5] + x1.z * rm[6] + x1.w * rm[7];
        float e = __expf(-p);
        g_S[b * Tt * Tt + (k0 + kl) * Tt + j] = __frcp_rn(1.f + e);
    }
}

// ---------------------------------------------------------------------------
// Kernel 4: E = v @ S (per batch), then softmax over j. Pure FMA GEMM.
// Grid: (Tt/TI, Bb) = 128 blocks. Thread j owns a column; 16 rows per block.
// ---------------------------------------------------------------------------
__global__ __launch_bounds__(256) void k_attn(
    const float* __restrict__ v, float* __restrict__ out)
{
    __shared__ __align__(16) float s_V[Tt * TI];   // [k][il] = v[i0+il, k]
    __shared__ __align__(16) float s_E[TI * Tt];

    const int j  = threadIdx.x;
    const int b  = blockIdx.y;
    const int i0 = blockIdx.x * TI;

    for (int idx = j; idx < TI * Tt; idx += 256) {
        int il = idx >> 8, k = idx & 255;
        s_V[k * TI + il] = v[(i0 + il) * Tt + k];
    }
    __syncthreads();

    float acc[TI];
#pragma unroll
    for (int il = 0; il < TI; il++) acc[il] = 0.f;

    const float* Sb = g_S + b * Tt * Tt + j;
#pragma unroll 8
    for (int k = 0; k < Tt; k++) {
        float s = Sb[k * Tt];
        const float4* vk = (const float4*)&s_V[k * TI];
#pragma unroll
        for (int qv = 0; qv < TI / 4; qv++) {
            float4 vv = vk[qv];
            acc[qv * 4 + 0] += vv.x * s;
            acc[qv * 4 + 1] += vv.y * s;
            acc[qv * 4 + 2] += vv.z * s;
            acc[qv * 4 + 3] += vv.w * s;
        }
    }

#pragma unroll
    for (int il = 0; il < TI; il++) s_E[il * Tt + j] = acc[il];
    __syncthreads();

    // Softmax: 8 warps, rows w and w+8
    const int w = j >> 5, lane = j & 31;
#pragma unroll
    for (int rr = 0; rr < TI / 8; rr++) {
        const int row = w + rr * 8;
        float m = -1e30f;
#pragma unroll
        for (int qi = 0; qi < Tt / 32; qi++)
            m = fmaxf(m, s_E[row * Tt + qi * 32 + lane]);
#pragma unroll
        for (int off = 16; off > 0; off >>= 1)
            m = fmaxf(m, __shfl_xor_sync(0xffffffffu, m, off));

        float e[Tt / 32];
        float sum = 0.f;
#pragma unroll
        for (int qi = 0; qi < Tt / 32; qi++) {
            e[qi] = __expf(s_E[row * Tt + qi * 32 + lane] - m);
            sum += e[qi];
        }
#pragma unroll
        for (int off = 16; off > 0; off >>= 1)
            sum += __shfl_xor_sync(0xffffffffu, sum, off);

        const float inv = __frcp_rn(sum);
        const size_t o = ((size_t)b * Tt + (i0 + row)) * Tt;
#pragma unroll
        for (int qi = 0; qi < Tt / 32; qi++)
            out[o + qi * 32 + lane] = e[qi] * inv;
    }
}

// ---------------------------------------------------------------------------
extern "C" void kernel_launch(void* const* d_in, const int* in_sizes, int n_in,
                              void* d_out, int out_size)
{
    const float* x  = (const float*)d_in[0];
    const float* u1 = (const float*)d_in[1];
    const float* u2 = (const float*)d_in[2];
    const float* u3 = (const float*)d_in[3];
    const float* bb = (const float*)d_in[4];
    const float* v  = (const float*)d_in[5];
    float* out = (float*)d_out;

    dim3 g1(NBLK, Bb);              // 1024 blocks
    k_reduce<<<g1, 256>>>(x, u1, u2, u3);

    k_reduce2<<<64, 128>>>();

    dim3 g2(Tt / KG, Bb);           // 128 blocks
    k_sig<<<g2, 256>>>(bb);

    dim3 g3(Tt / TI, Bb);           // 128 blocks
    k_attn<<<g3, 256>>>(v, out);
}

// round 4
// speedup vs baseline: 2.4475x; 1.2006x over previous
#include <cuda_runtime.h>

#define Bb 8
#define Nn 4096
#define Cc 8
#define Tt 256
#define NPB 32                 // n-values per block in k_reduce
#define NBLK (Nn / NPB)        // 128 n-blocks per batch
#define TQ (Tt / 4)            // 64 float4 quads over t
#define KG 8                   // k's per block in k_sig
#define TI 8                   // output rows per block in k_attn
#define KC 32                  // k-rows per staged S chunk in k_attn
#define NCH (Tt / KC)          // 8 chunks

// Per-block partial sums: [Bb*NBLK][2][Cc][TQ] float4 = 16 MB (L2-resident)
__device__ float4 g_part[Bb * NBLK * 2 * Cc * TQ];
__device__ float  g_xu1[Bb * Cc * Tt];    // x_u1 as [b][c][t]
__device__ float  g_M  [Bb * Cc * Tt];    // M[b][c][s]
__device__ float  g_S  [Bb * Tt * Tt];    // sigmoid(product + bias), 2 MB

// ---------------------------------------------------------------------------
// Kernel 1: single streaming pass over x (256 MB), vectorized float4.
// (unchanged — measured at 75.8% DRAM, near roofline)
// ---------------------------------------------------------------------------
__global__ __launch_bounds__(256, 3) void k_reduce(
    const float* __restrict__ x,  const float* __restrict__ u1,
    const float* __restrict__ u2, const float* __restrict__ u3)
{
    __shared__ float s_u1[NPB];
    __shared__ float s_u2[Cc * NPB];

    const int tid    = threadIdx.x;
    const int lane   = tid & 31;
    const int warp   = tid >> 5;
    const int qg     = lane & 7;
    const int n_sub  = (lane >> 3) & 1;
    const int c_half = lane >> 4;
    const int q      = warp * 8 + qg;

    const int b  = blockIdx.y;
    const int n0 = blockIdx.x * NPB;

    if (tid < NPB) s_u1[tid] = u1[n0 + tid];
    {
        int c = tid >> 5, nn = tid & 31;
        s_u2[tid] = u2[c * Nn + n0 + nn];
    }
    float c3[4];
#pragma unroll
    for (int cc = 0; cc < 4; cc++) c3[cc] = u3[c_half * 4 + cc];
    __syncthreads();

    const float4* xb = (const float4*)x
                     + ((size_t)b * Nn + n0) * (Cc * TQ)
                     + c_half * 4 * TQ + q;

    float4 ax[4], am[4];
#pragma unroll
    for (int cc = 0; cc < 4; cc++) {
        ax[cc] = make_float4(0.f, 0.f, 0.f, 0.f);
        am[cc] = make_float4(0.f, 0.f, 0.f, 0.f);
    }

#pragma unroll
    for (int i = 0; i < NPB / 2; i++) {
        const int n = i * 2 + n_sub;
        const float4* xn = xb + (size_t)n * (Cc * TQ);

        float4 vals[4];
#pragma unroll
        for (int cc = 0; cc < 4; cc++) vals[cc] = xn[cc * TQ];

        float4 r = make_float4(0.f, 0.f, 0.f, 0.f);
#pragma unroll
        for (int cc = 0; cc < 4; cc++) {
            r.x += vals[cc].x * c3[cc];
            r.y += vals[cc].y * c3[cc];
            r.z += vals[cc].z * c3[cc];
            r.w += vals[cc].w * c3[cc];
        }
        r.x += __shfl_xor_sync(0xffffffffu, r.x, 16);
        r.y += __shfl_xor_sync(0xffffffffu, r.y, 16);
        r.z += __shfl_xor_sync(0xffffffffu, r.z, 16);
        r.w += __shfl_xor_sync(0xffffffffu, r.w, 16);

        const float un = s_u1[n];
#pragma unroll
        for (int cc = 0; cc < 4; cc++) {
            ax[cc].x += vals[cc].x * un;
            ax[cc].y += vals[cc].y * un;
            ax[cc].z += vals[cc].z * un;
            ax[cc].w += vals[cc].w * un;
            const float w = s_u2[(c_half * 4 + cc) * NPB + n];
            am[cc].x += r.x * w;
            am[cc].y += r.y * w;
            am[cc].z += r.z * w;
            am[cc].w += r.w * w;
        }
    }

#pragma unroll
    for (int cc = 0; cc < 4; cc++) {
        ax[cc].x += __shfl_xor_sync(0xffffffffu, ax[cc].x, 8);
        ax[cc].y += __shfl_xor_sync(0xffffffffu, ax[cc].y, 8);
        ax[cc].z += __shfl_xor_sync(0xffffffffu, ax[cc].z, 8);
        ax[cc].w += __shfl_xor_sync(0xffffffffu, ax[cc].w, 8);
        am[cc].x += __shfl_xor_sync(0xffffffffu, am[cc].x, 8);
        am[cc].y += __shfl_xor_sync(0xffffffffu, am[cc].y, 8);
        am[cc].z += __shfl_xor_sync(0xffffffffu, am[cc].z, 8);
        am[cc].w += __shfl_xor_sync(0xffffffffu, am[cc].w, 8);
    }

    if (n_sub == 0) {
        float4* gp = g_part + (size_t)(b * NBLK + blockIdx.x) * (2 * Cc * TQ);
#pragma unroll
        for (int cc = 0; cc < 4; cc++) {
            const int c = c_half * 4 + cc;
            gp[c * TQ + q]           = ax[cc];
            gp[Cc * TQ + c * TQ + q] = am[cc];
        }
    }
}

// ---------------------------------------------------------------------------
// Kernel 2: reduce 128 per-block partials -> g_xu1, g_M.
// 4-way k-split per output element + smem tree (latency chain 128 -> 32).
// ---------------------------------------------------------------------------
__global__ __launch_bounds__(512) void k_reduce2()
{
    __shared__ float4 red[4][128];

    const int t   = threadIdx.x;
    const int tx  = t & 127;
    const int ty  = t >> 7;                       // 0..3
    const int idx = blockIdx.x * 128 + tx;        // 0..8191
    const int b   = idx >> 10;
    const int rem = idx & 1023;

    const float4* gp = g_part + (size_t)b * NBLK * (2 * Cc * TQ) + rem
                     + (size_t)ty * (NBLK / 4) * (2 * Cc * TQ);
    float4 s = make_float4(0.f, 0.f, 0.f, 0.f);
#pragma unroll 8
    for (int k = 0; k < NBLK / 4; k++) {
        float4 v = gp[(size_t)k * (2 * Cc * TQ)];
        s.x += v.x; s.y += v.y; s.z += v.z; s.w += v.w;
    }
    red[ty][tx] = s;
    __syncthreads();

    if (ty == 0) {
        float4 a = red[0][tx], b2 = red[1][tx], c = red[2][tx], d = red[3][tx];
        s.x = (a.x + b2.x) + (c.x + d.x);
        s.y = (a.y + b2.y) + (c.y + d.y);
        s.z = (a.z + b2.z) + (c.z + d.z);
        s.w = (a.w + b2.w) + (c.w + d.w);
        if (rem < Cc * TQ) ((float4*)g_xu1)[b * (Cc * TQ) + rem] = s;
        else               ((float4*)g_M  )[b * (Cc * TQ) + rem - Cc * TQ] = s;
    }
}

// ---------------------------------------------------------------------------
// Kernel 3: S[b,k,j] = sigmoid( sum_c x_u1[b,c,k]*M[b,c,j] + bias[k,j] )
// Grid: (Tt/KG, Bb) = 256 blocks.
// ---------------------------------------------------------------------------
__global__ __launch_bounds__(256) void k_sig(const float* __restrict__ bias)
{
    __shared__ __align__(16) float s_M[Cc * Tt];
    __shared__ __align__(16) float s_X[KG * Cc];

    const int j  = threadIdx.x;
    const int b  = blockIdx.y;
    const int k0 = blockIdx.x * KG;

    for (int idx = j; idx < Cc * Tt; idx += 256)
        s_M[idx] = g_M[b * Cc * Tt + idx];
    if (j < KG * Cc) {
        int kl = j >> 3, c = j & 7;
        s_X[kl * Cc + c] = g_xu1[b * Cc * Tt + c * Tt + (k0 + kl)];
    }
    __syncthreads();

    float rm[Cc];
#pragma unroll
    for (int c = 0; c < Cc; c++) rm[c] = s_M[c * Tt + j];

#pragma unroll
    for (int kl = 0; kl < KG; kl++) {
        float4 x0 = *(const float4*)&s_X[kl * Cc + 0];
        float4 x1 = *(const float4*)&s_X[kl * Cc + 4];
        float p = bias[(k0 + kl) * Tt + j];
        p += x0.x * rm[0] + x0.y * rm[1] + x0.z * rm[2] + x0.w * rm[3]
           + x1.x * rm[4] + x1.y * rm[5] + x1.z * rm[6] + x1.w * rm[7];
        float e = __expf(-p);
        g_S[b * Tt * Tt + (k0 + kl) * Tt + j] = __frcp_rn(1.f + e);
    }
}

// ---------------------------------------------------------------------------
// Kernel 4: E = v @ S (per batch) then softmax over j.
// 256 blocks (TI=8). S streamed through double-buffered smem chunks with
// loads prefetched into registers one chunk ahead (latency hidden by FMAs).
// ---------------------------------------------------------------------------
__global__ __launch_bounds__(256, 2) void k_attn(
    const float* __restrict__ v, float* __restrict__ out)
{
    __shared__ __align__(16) float s_S[2][KC * Tt];  // 2 x 32 KB
    __shared__ __align__(16) float s_V[Tt * TI];     // [k][il]
    __shared__ __align__(16) float s_E[TI * Tt];

    const int j  = threadIdx.x;
    const int b  = blockIdx.y;
    const int i0 = blockIdx.x * TI;

    for (int idx = j; idx < TI * Tt; idx += 256) {
        int il = idx >> 8, k = idx & 255;
        s_V[k * TI + il] = v[(i0 + il) * Tt + k];
    }

    const float4* Sb = (const float4*)(g_S + (size_t)b * Tt * Tt);

    float4 pre[8];
#pragma unroll
    for (int i = 0; i < 8; i++) pre[i] = Sb[i * 256 + j];   // chunk 0

    float acc[TI];
#pragma unroll
    for (int il = 0; il < TI; il++) acc[il] = 0.f;

    for (int ch = 0; ch < NCH; ch++) {
        float4* buf = (float4*)s_S[ch & 1];
#pragma unroll
        for (int i = 0; i < 8; i++) buf[i * 256 + j] = pre[i];
        if (ch + 1 < NCH) {
            const float4* nxt = Sb + (size_t)(ch + 1) * KC * (Tt / 4);
#pragma unroll
            for (int i = 0; i < 8; i++) pre[i] = nxt[i * 256 + j];
        }
        __syncthreads();

        const float* Sc = s_S[ch & 1];
#pragma unroll
        for (int kk = 0; kk < KC; kk++) {
            float s = Sc[kk * Tt + j];
            const float4* vk = (const float4*)&s_V[(ch * KC + kk) * TI];
            float4 v0 = vk[0], v1 = vk[1];
            acc[0] += v0.x * s;  acc[1] += v0.y * s;
            acc[2] += v0.z * s;  acc[3] += v0.w * s;
            acc[4] += v1.x * s;  acc[5] += v1.y * s;
            acc[6] += v1.z * s;  acc[7] += v1.w * s;
        }
        __syncthreads();
    }

#pragma unroll
    for (int il = 0; il < TI; il++) s_E[il * Tt + j] = acc[il];
    __syncthreads();

    // Softmax: warp w owns row w (TI == 8 == warps/block)
    const int w = j >> 5, lane = j & 31;
    float m = -1e30f;
#pragma unroll
    for (int qi = 0; qi < Tt / 32; qi++)
        m = fmaxf(m, s_E[w * Tt + qi * 32 + lane]);
#pragma unroll
    for (int off = 16; off > 0; off >>= 1)
        m = fmaxf(m, __shfl_xor_sync(0xffffffffu, m, off));

    float e[Tt / 32];
    float sum = 0.f;
#pragma unroll
    for (int qi = 0; qi < Tt / 32; qi++) {
        e[qi] = __expf(s_E[w * Tt + qi * 32 + lane] - m);
        sum += e[qi];
    }
#pragma unroll
    for (int off = 16; off > 0; off >>= 1)
        sum += __shfl_xor_sync(0xffffffffu, sum, off);

    const float inv = __frcp_rn(sum);
    const size_t o = ((size_t)b * Tt + (i0 + w)) * Tt;
#pragma unroll
    for (int qi = 0; qi < Tt / 32; qi++)
        out[o + qi * 32 + lane] = e[qi] * inv;
}

// ---------------------------------------------------------------------------
extern "C" void kernel_launch(void* const* d_in, const int* in_sizes, int n_in,
                              void* d_out, int out_size)
{
    const float* x  = (const float*)d_in[0];
    const float* u1 = (const float*)d_in[1];
    const float* u2 = (const float*)d_in[2];
    const float* u3 = (const float*)d_in[3];
    const float* bb = (const float*)d_in[4];
    const float* v  = (const float*)d_in[5];
    float* out = (float*)d_out;

    dim3 g1(NBLK, Bb);              // 1024 blocks
    k_reduce<<<g1, 256>>>(x, u1, u2, u3);

    k_reduce2<<<64, 512>>>();

    dim3 g2(Tt / KG, Bb);           // 256 blocks
    k_sig<<<g2, 256>>>(bb);

    dim3 g3(Tt / TI, Bb);           // 256 blocks
    k_attn<<<g3, 256>>>(v, out);
}

// round 6
// speedup vs baseline: 2.7506x; 1.1238x over previous
#include <cuda_runtime.h>
#include <cstdint>

#define Bb 8
#define Nn 4096
#define Cc 8
#define Tt 256
#define NPB 32                 // n-values per block in k_reduce
#define NBLK (Nn / NPB)        // 128 n-blocks per batch
#define TQ (Tt / 4)            // 64 float4 quads over t
#define KG 8                   // k's per block in k_sig
#define TI 8                   // output rows per block in k_attn
#define KC 16                  // k-rows per staged S chunk in k_attn
#define NCH (Tt / KC)          // 16 chunks

// Per-block partial sums: [Bb*NBLK][2][Cc][TQ] float4 = 16 MB (L2-resident)
__device__ float4 g_part[Bb * NBLK * 2 * Cc * TQ];
__device__ float  g_xu1[Bb * Cc * Tt];    // x_u1 as [b][c][t]
__device__ float  g_M  [Bb * Cc * Tt];    // M[b][c][s]
__device__ float  g_S  [Bb * Tt * Tt];    // sigmoid(product + bias), 2 MB

// cp.async helpers
#define CP_ASYNC16(dst_u32, src_ptr) \
    asm volatile("cp.async.cg.shared.global [%0], [%1], 16;" :: "r"(dst_u32), "l"(src_ptr))
#define CP_COMMIT()  asm volatile("cp.async.commit_group;")
#define CP_WAIT(n)   asm volatile("cp.async.wait_group %0;" :: "n"(n))

// ---------------------------------------------------------------------------
// Kernel 1: single streaming pass over x (256 MB), vectorized float4.
// (at DRAM roofline; only change: __ldcs streaming hint on x)
// ---------------------------------------------------------------------------
__global__ __launch_bounds__(256, 3) void k_reduce(
    const float* __restrict__ x,  const float* __restrict__ u1,
    const float* __restrict__ u2, const float* __restrict__ u3)
{
    __shared__ float s_u1[NPB];
    __shared__ float s_u2[Cc * NPB];

    const int tid    = threadIdx.x;
    const int lane   = tid & 31;
    const int warp   = tid >> 5;
    const int qg     = lane & 7;
    const int n_sub  = (lane >> 3) & 1;
    const int c_half = lane >> 4;
    const int q      = warp * 8 + qg;

    const int b  = blockIdx.y;
    const int n0 = blockIdx.x * NPB;

    if (tid < NPB) s_u1[tid] = u1[n0 + tid];
    {
        int c = tid >> 5, nn = tid & 31;
        s_u2[tid] = u2[c * Nn + n0 + nn];
    }
    float c3[4];
#pragma unroll
    for (int cc = 0; cc < 4; cc++) c3[cc] = u3[c_half * 4 + cc];
    __syncthreads();

    const float4* xb = (const float4*)x
                     + ((size_t)b * Nn + n0) * (Cc * TQ)
                     + c_half * 4 * TQ + q;

    float4 ax[4], am[4];
#pragma unroll
    for (int cc = 0; cc < 4; cc++) {
        ax[cc] = make_float4(0.f, 0.f, 0.f, 0.f);
        am[cc] = make_float4(0.f, 0.f, 0.f, 0.f);
    }

#pragma unroll
    for (int i = 0; i < NPB / 2; i++) {
        const int n = i * 2 + n_sub;
        const float4* xn = xb + (size_t)n * (Cc * TQ);

        float4 vals[4];
#pragma unroll
        for (int cc = 0; cc < 4; cc++) vals[cc] = __ldcs(xn + cc * TQ);

        float4 r = make_float4(0.f, 0.f, 0.f, 0.f);
#pragma unroll
        for (int cc = 0; cc < 4; cc++) {
            r.x += vals[cc].x * c3[cc];
            r.y += vals[cc].y * c3[cc];
            r.z += vals[cc].z * c3[cc];
            r.w += vals[cc].w * c3[cc];
        }
        r.x += __shfl_xor_sync(0xffffffffu, r.x, 16);
        r.y += __shfl_xor_sync(0xffffffffu, r.y, 16);
        r.z += __shfl_xor_sync(0xffffffffu, r.z, 16);
        r.w += __shfl_xor_sync(0xffffffffu, r.w, 16);

        const float un = s_u1[n];
#pragma unroll
        for (int cc = 0; cc < 4; cc++) {
            ax[cc].x += vals[cc].x * un;
            ax[cc].y += vals[cc].y * un;
            ax[cc].z += vals[cc].z * un;
            ax[cc].w += vals[cc].w * un;
            const float w = s_u2[(c_half * 4 + cc) * NPB + n];
            am[cc].x += r.x * w;
            am[cc].y += r.y * w;
            am[cc].z += r.z * w;
            am[cc].w += r.w * w;
        }
    }

#pragma unroll
    for (int cc = 0; cc < 4; cc++) {
        ax[cc].x += __shfl_xor_sync(0xffffffffu, ax[cc].x, 8);
        ax[cc].y += __shfl_xor_sync(0xffffffffu, ax[cc].y, 8);
        ax[cc].z += __shfl_xor_sync(0xffffffffu, ax[cc].z, 8);
        ax[cc].w += __shfl_xor_sync(0xffffffffu, ax[cc].w, 8);
        am[cc].x += __shfl_xor_sync(0xffffffffu, am[cc].x, 8);
        am[cc].y += __shfl_xor_sync(0xffffffffu, am[cc].y, 8);
        am[cc].z += __shfl_xor_sync(0xffffffffu, am[cc].z, 8);
        am[cc].w += __shfl_xor_sync(0xffffffffu, am[cc].w, 8);
    }

    if (n_sub == 0) {
        float4* gp = g_part + (size_t)(b * NBLK + blockIdx.x) * (2 * Cc * TQ);
#pragma unroll
        for (int cc = 0; cc < 4; cc++) {
            const int c = c_half * 4 + cc;
            gp[c * TQ + q]           = ax[cc];
            gp[Cc * TQ + c * TQ + q] = am[cc];
        }
    }
}

// ---------------------------------------------------------------------------
// Kernel 2: reduce 128 per-block partials -> g_xu1, g_M.
// ---------------------------------------------------------------------------
__global__ __launch_bounds__(512) void k_reduce2()
{
    __shared__ float4 red[4][128];

    const int t   = threadIdx.x;
    const int tx  = t & 127;
    const int ty  = t >> 7;
    const int idx = blockIdx.x * 128 + tx;
    const int b   = idx >> 10;
    const int rem = idx & 1023;

    const float4* gp = g_part + (size_t)b * NBLK * (2 * Cc * TQ) + rem
                     + (size_t)ty * (NBLK / 4) * (2 * Cc * TQ);
    float4 s = make_float4(0.f, 0.f, 0.f, 0.f);
#pragma unroll 8
    for (int k = 0; k < NBLK / 4; k++) {
        float4 v = gp[(size_t)k * (2 * Cc * TQ)];
        s.x += v.x; s.y += v.y; s.z += v.z; s.w += v.w;
    }
    red[ty][tx] = s;
    __syncthreads();

    if (ty == 0) {
        float4 a = red[0][tx], b2 = red[1][tx], c = red[2][tx], d = red[3][tx];
        s.x = (a.x + b2.x) + (c.x + d.x);
        s.y = (a.y + b2.y) + (c.y + d.y);
        s.z = (a.z + b2.z) + (c.z + d.z);
        s.w = (a.w + b2.w) + (c.w + d.w);
        if (rem < Cc * TQ) ((float4*)g_xu1)[b * (Cc * TQ) + rem] = s;
        else               ((float4*)g_M  )[b * (Cc * TQ) + rem - Cc * TQ] = s;
    }
}

// ---------------------------------------------------------------------------
// Kernel 3: S[b,k,j] = sigmoid( sum_c x_u1[b,c,k]*M[b,c,j] + bias[k,j] )
// ---------------------------------------------------------------------------
__global__ __launch_bounds__(256) void k_sig(const float* __restrict__ bias)
{
    __shared__ __align__(16) float s_M[Cc * Tt];
    __shared__ __align__(16) float s_X[KG * Cc];

    const int j  = threadIdx.x;
    const int b  = blockIdx.y;
    const int k0 = blockIdx.x * KG;

    for (int idx = j; idx < Cc * Tt; idx += 256)
        s_M[idx] = g_M[b * Cc * Tt + idx];
    if (j < KG * Cc) {
        int kl = j >> 3, c = j & 7;
        s_X[kl * Cc + c] = g_xu1[b * Cc * Tt + c * Tt + (k0 + kl)];
    }
    __syncthreads();

    float rm[Cc];
#pragma unroll
    for (int c = 0; c < Cc; c++) rm[c] = s_M[c * Tt + j];

#pragma unroll
    for (int kl = 0; kl < KG; kl++) {
        float4 x0 = *(const float4*)&s_X[kl * Cc + 0];
        float4 x1 = *(const float4*)&s_X[kl * Cc + 4];
        float p = bias[(k0 + kl) * Tt + j];
        p += x0.x * rm[0] + x0.y * rm[1] + x0.z * rm[2] + x0.w * rm[3]
           + x1.x * rm[4] + x1.y * rm[5] + x1.z * rm[6] + x1.w * rm[7];
        float e = __expf(-p);
        g_S[b * Tt * Tt + (k0 + kl) * Tt + j] = __frcp_rn(1.f + e);
    }
}

// ---------------------------------------------------------------------------
// Kernel 4: E = v @ S (per batch) then softmax over j.
// S staged GMEM->SMEM with cp.async double buffering (no register transit).
// smem ~40KB, low regs -> ~4-5 blocks/SM resident.
// ---------------------------------------------------------------------------
__global__ __launch_bounds__(256, 4) void k_attn(
    const float* __restrict__ v, float* __restrict__ out)
{
    __shared__ __align__(16) float s_S[2][KC * Tt];  // 2 x 16 KB
    __shared__ __align__(16) float s_V[Tt * TI];     // 8 KB, [k][il]

    float* s_E = s_S[0];  // aliased after the GEMM loop

    const int j  = threadIdx.x;
    const int b  = blockIdx.y;
    const int i0 = blockIdx.x * TI;

    const char* Sg = (const char*)(g_S + (size_t)b * Tt * Tt);
    unsigned int sb[2];
    sb[0] = (unsigned int)__cvta_generic_to_shared(s_S[0]);
    sb[1] = (unsigned int)__cvta_generic_to_shared(s_S[1]);

    // stage chunk 0
#pragma unroll
    for (int tq = 0; tq < 4; tq++)
        CP_ASYNC16(sb[0] + tq * 4096 + j * 16, Sg + tq * 4096 + j * 16);
    CP_COMMIT();

    for (int idx = j; idx < TI * Tt; idx += 256) {
        int il = idx >> 8, k = idx & 255;
        s_V[k * TI + il] = v[(i0 + il) * Tt + k];
    }

    float acc[TI];
#pragma unroll
    for (int il = 0; il < TI; il++) acc[il] = 0.f;

    for (int ch = 0; ch < NCH; ch++) {
        if (ch + 1 < NCH) {
            const char* src = Sg + (size_t)(ch + 1) * KC * Tt * 4;
            const unsigned int dst = sb[(ch + 1) & 1];
#pragma unroll
            for (int tq = 0; tq < 4; tq++)
                CP_ASYNC16(dst + tq * 4096 + j * 16, src + tq * 4096 + j * 16);
            CP_COMMIT();
            CP_WAIT(1);
        } else {
            CP_WAIT(0);
        }
        __syncthreads();

        const float* Sc = s_S[ch & 1];
#pragma unroll
        for (int kk = 0; kk < KC; kk++) {
            float s = Sc[kk * Tt + j];
            const float4* vk = (const float4*)&s_V[(ch * KC + kk) * TI];
            float4 v0 = vk[0], v1 = vk[1];
            acc[0] += v0.x * s;  acc[1] += v0.y * s;
            acc[2] += v0.z * s;  acc[3] += v0.w * s;
            acc[4] += v1.x * s;  acc[5] += v1.y * s;
            acc[6] += v1.z * s;  acc[7] += v1.w * s;
        }
        __syncthreads();
    }

#pragma unroll
    for (int il = 0; il < TI; il++) s_E[il * Tt + j] = acc[il];
    __syncthreads();

    // Softmax: warp w owns row w (TI == 8 == warps/block)
    const int w = j >> 5, lane = j & 31;
    float m = -1e30f;
#pragma unroll
    for (int qi = 0; qi < Tt / 32; qi++)
        m = fmaxf(m, s_E[w * Tt + qi * 32 + lane]);
#pragma unroll
    for (int off = 16; off > 0; off >>= 1)
        m = fmaxf(m, __shfl_xor_sync(0xffffffffu, m, off));

    float e[Tt / 32];
    float sum = 0.f;
#pragma unroll
    for (int qi = 0; qi < Tt / 32; qi++) {
        e[qi] = __expf(s_E[w * Tt + qi * 32 + lane] - m);
        sum += e[qi];
    }
#pragma unroll
    for (int off = 16; off > 0; off >>= 1)
        sum += __shfl_xor_sync(0xffffffffu, sum, off);

    const float inv = __frcp_rn(sum);
    const size_t o = ((size_t)b * Tt + (i0 + w)) * Tt;
#pragma unroll
    for (int qi = 0; qi < Tt / 32; qi++)
        out[o + qi * 32 + lane] = e[qi] * inv;
}

// ---------------------------------------------------------------------------
extern "C" void kernel_launch(void* const* d_in, const int* in_sizes, int n_in,
                              void* d_out, int out_size)
{
    const float* x  = (const float*)d_in[0];
    const float* u1 = (const float*)d_in[1];
    const float* u2 = (const float*)d_in[2];
    const float* u3 = (const float*)d_in[3];
    const float* bb = (const float*)d_in[4];
    const float* v  = (const float*)d_in[5];
    float* out = (float*)d_out;

    dim3 g1(NBLK, Bb);              // 1024 blocks
    k_reduce<<<g1, 256>>>(x, u1, u2, u3);

    k_reduce2<<<64, 512>>>();

    dim3 g2(Tt / KG, Bb);           // 256 blocks
    k_sig<<<g2, 256>>>(bb);

    dim3 g3(Tt / TI, Bb);           // 256 blocks
    k_attn<<<g3, 256>>>(v, out);
}